// round 15
// baseline (speedup 1.0000x reference)
#include <cuda_runtime.h>
#include <cuda_bf16.h>
#include <cstdint>
#include <math.h>

// Problem constants (fixed by the reference: B=4, L=8192, D=1024, H=16)
#define B_   4
#define L_   8192
#define D_   1024
#define H_   16
#define DH   64
#define M_   (B_*L_)          // 32768 rows
#define KD   1024             // GEMM K dim
#define ND   1024             // GEMM N dim
#define LCH  16               // split-K chunks over L for the Kv reduction
#define CHL  (L_/LCH)         // 512 rows per chunk

// ---------------------------------------------------------------------------
// Scratch: __device__ globals (allocation-free per harness rules)
// ---------------------------------------------------------------------------
__device__ float g_Qf[(size_t)M_*D_];     // phi(Q) fp32
__device__ float g_Kf[(size_t)M_*D_];     // phi(K) fp32
__device__ float g_V [(size_t)M_*D_];     // V fp32
__device__ float g_KvPart[(size_t)B_*H_*LCH*DH*DH];
__device__ float g_K1Part[(size_t)B_*H_*LCH*DH];
__device__ float g_Kv[(size_t)B_*H_*DH*DH];
__device__ float g_K1[(size_t)B_*H_*DH];

// bf16 hi/lo split operands for tensor-core GEMMs
__device__ __nv_bfloat16 g_xh[(size_t)M_*D_], g_xl[(size_t)M_*D_];   // x
__device__ __nv_bfloat16 g_ah[(size_t)M_*D_], g_al[(size_t)M_*D_];   // attn out
__device__ __nv_bfloat16 g_Wh[4][(size_t)D_*D_], g_Wl[4][(size_t)D_*D_];

__device__ __forceinline__ float phi_f(float x) {
    return (x > 0.f) ? (x + 1.f) : expf(x);   // elu(x)+1
}

// k-pair permutation: u32 slot p(kp) holds original k-pair kp, so that the
// mma fragment pair (kp=tg, kp=tg+4) sits in adjacent u32 slots (2tg, 2tg+1)
// and loads as a single LDS.64.
__device__ __forceinline__ int kperm(int kp) { return ((kp & 3) << 1) | (kp >> 2); }

// ---------------------------------------------------------------------------
// fp32 -> (bf16 hi, bf16 lo) split conversion.  DST: 0=x, 1..4=W[DST-1]
// ---------------------------------------------------------------------------
template<int DST>
__global__ void __launch_bounds__(256)
convert_k(const float* __restrict__ src, int n4)
{
    __nv_bfloat16* hi = (DST == 0) ? g_xh
                      : (DST == 1) ? g_Wh[0]
                      : (DST == 2) ? g_Wh[1]
                      : (DST == 3) ? g_Wh[2] : g_Wh[3];
    __nv_bfloat16* lo = (DST == 0) ? g_xl
                      : (DST == 1) ? g_Wl[0]
                      : (DST == 2) ? g_Wl[1]
                      : (DST == 3) ? g_Wl[2] : g_Wl[3];

    int i = blockIdx.x * 256 + threadIdx.x;
    if (i >= n4) return;
    float4 v = ((const float4*)src)[i];

    __nv_bfloat16 h0 = __float2bfloat16(v.x);
    __nv_bfloat16 h1 = __float2bfloat16(v.y);
    __nv_bfloat16 h2 = __float2bfloat16(v.z);
    __nv_bfloat16 h3 = __float2bfloat16(v.w);
    __nv_bfloat16 l0 = __float2bfloat16(v.x - __bfloat162float(h0));
    __nv_bfloat16 l1 = __float2bfloat16(v.y - __bfloat162float(h1));
    __nv_bfloat16 l2 = __float2bfloat16(v.z - __bfloat162float(h2));
    __nv_bfloat16 l3 = __float2bfloat16(v.w - __bfloat162float(h3));

    __nv_bfloat162 hp0(h0, h1), hp1(h2, h3), lp0(l0, l1), lp1(l2, l3);
    uint2 hu, lu;
    hu.x = *reinterpret_cast<uint32_t*>(&hp0);
    hu.y = *reinterpret_cast<uint32_t*>(&hp1);
    lu.x = *reinterpret_cast<uint32_t*>(&lp0);
    lu.y = *reinterpret_cast<uint32_t*>(&lp1);
    ((uint2*)hi)[i] = hu;
    ((uint2*)lo)[i] = lu;
}

// ---------------------------------------------------------------------------
// bf16-split tensor-core GEMM: C[M,N] = A@B with A=(Ah+Al), B=(Bh+Bl),
// C = Ah*Bh + Ah*Bl + Al*Bh, fp32 accum via mma.sync.m16n8k16.
// CTA: 512 thr, tile 128x128, kstep=16, double-buffered smem.
// Warp grid 4(m) x 4(n); warp tile 32(m) x 32(n) -> 16 warps/SM for latency
// hiding. Fragment loads are LDS.64 via the k-pair permutation.
// ---------------------------------------------------------------------------
__device__ __forceinline__ void mma_bf16(float* acc, const uint32_t* a,
                                         uint32_t b0, uint32_t b1)
{
    asm volatile(
        "mma.sync.aligned.m16n8k16.row.col.f32.bf16.bf16.f32 "
        "{%0,%1,%2,%3}, {%4,%5,%6,%7}, {%8,%9}, {%0,%1,%2,%3};\n"
        : "+f"(acc[0]), "+f"(acc[1]), "+f"(acc[2]), "+f"(acc[3])
        : "r"(a[0]), "r"(a[1]), "r"(a[2]), "r"(a[3]), "r"(b0), "r"(b1));
}

#define SA 10   // padded u32 row stride (8 k-pair slots + 2 pad, even for LDS.64)

template<int ACT, int ASRC, int WIDX, int DST>
__global__ void __launch_bounds__(512, 1)
bgemm_k(float* __restrict__ C_ext)
{
    const uint32_t* Ah32 = (const uint32_t*)((ASRC == 0) ? g_xh : g_ah);
    const uint32_t* Al32 = (const uint32_t*)((ASRC == 0) ? g_xl : g_al);
    const __nv_bfloat16* Wh = g_Wh[WIDX];
    const __nv_bfloat16* Wl = g_Wl[WIDX];
    float* C = (DST == 0) ? (float*)g_Qf
             : (DST == 1) ? (float*)g_Kf
             : (DST == 2) ? (float*)g_V
             : C_ext;

    // smem: [stage][hi/lo][128 * SA] u32, k-pair-permuted
    __shared__ __align__(16) uint32_t As[2][2][128 * SA];
    __shared__ __align__(16) uint32_t Bs[2][2][128 * SA];

    const int tid = threadIdx.x;
    const int bn = blockIdx.x * 128;
    const int bm = blockIdx.y * 128;

    const int warp = tid >> 5;         // 0..15
    const int lane = tid & 31;
    const int m0 = (warp & 3) * 32;    // warp m offset
    const int n0 = (warp >> 2) * 32;   // warp n offset
    const int g  = lane >> 2;          // group id (0..7)
    const int tg = lane & 3;           // thread-in-group

    // A load mapping: u32 i = tid + 512j -> row=(tid>>3)+64j, kp=tid&7
    const int ar = tid >> 3;           // 0..63
    const int akp = tid & 7;
    const int akp_p = kperm(akp);
    // B load mapping: u32 i = tid + 512j -> k=(tid>>6)+8j, n-pair=tid&63
    const int bk = tid >> 6;           // 0..7
    const int bnp = tid & 63;
    const int bn2 = bnp * 2;

    float acc[2][4][4];
    #pragma unroll
    for (int mt = 0; mt < 2; mt++)
        #pragma unroll
        for (int nt = 0; nt < 4; nt++)
            #pragma unroll
            for (int e = 0; e < 4; e++) acc[mt][nt][e] = 0.f;

    uint32_t pah[2], pal[2], pbh[2], pbl[2];

    // ---- load one k-slab (kk) into regs ----
    auto load_regs = [&](int kk) {
        #pragma unroll
        for (int j = 0; j < 2; j++) {
            const int row = ar + 64 * j;
            const size_t gi = (size_t)(bm + row) * (KD / 2) + (kk >> 1) + akp;
            pah[j] = Ah32[gi];
            pal[j] = Al32[gi];
        }
        #pragma unroll
        for (int j = 0; j < 2; j++) {
            const int k = bk + 8 * j;
            const size_t gi = (size_t)(kk + k) * ND + bn + bn2;
            pbh[j] = *(const uint32_t*)(Wh + gi);
            pbl[j] = *(const uint32_t*)(Wl + gi);
        }
    };

    // ---- commit regs to smem stage s (permuted k layout) ----
    auto store_smem = [&](int s) {
        #pragma unroll
        for (int j = 0; j < 2; j++) {
            const int row = ar + 64 * j;
            As[s][0][row * SA + akp_p] = pah[j];
            As[s][1][row * SA + akp_p] = pal[j];
        }
        uint16_t* B0 = (uint16_t*)&Bs[s][0][0];
        uint16_t* B1 = (uint16_t*)&Bs[s][1][0];
        #pragma unroll
        for (int j = 0; j < 2; j++) {
            const int k = bk + 8 * j;                       // element k 0..15
            const int c = (kperm(k >> 1) << 1) | (k & 1);   // permuted u16 col
            B0[(bn2)     * (2 * SA) + c] = (uint16_t)(pbh[j] & 0xFFFF);
            B0[(bn2 + 1) * (2 * SA) + c] = (uint16_t)(pbh[j] >> 16);
            B1[(bn2)     * (2 * SA) + c] = (uint16_t)(pbl[j] & 0xFFFF);
            B1[(bn2 + 1) * (2 * SA) + c] = (uint16_t)(pbl[j] >> 16);
        }
    };

    // prologue
    load_regs(0);
    store_smem(0);
    __syncthreads();

    int buf = 0;
    for (int k0 = 0; k0 < KD; k0 += 16) {
        const bool has_next = (k0 + 16) < KD;
        if (has_next) load_regs(k0 + 16);

        // A fragments (hi & lo) for both m-tiles — LDS.64 pairs
        uint32_t fah[2][4], fal[2][4];
        #pragma unroll
        for (int mt = 0; mt < 2; mt++) {
            const int r = m0 + mt * 16 + g;
            const uint2 vh0 = *(const uint2*)&As[buf][0][r * SA + 2 * tg];
            const uint2 vh1 = *(const uint2*)&As[buf][0][(r + 8) * SA + 2 * tg];
            const uint2 vl0 = *(const uint2*)&As[buf][1][r * SA + 2 * tg];
            const uint2 vl1 = *(const uint2*)&As[buf][1][(r + 8) * SA + 2 * tg];
            fah[mt][0] = vh0.x; fah[mt][1] = vh1.x; fah[mt][2] = vh0.y; fah[mt][3] = vh1.y;
            fal[mt][0] = vl0.x; fal[mt][1] = vl1.x; fal[mt][2] = vl0.y; fal[mt][3] = vl1.y;
        }

        #pragma unroll
        for (int nt = 0; nt < 4; nt++) {
            const int n = n0 + nt * 8 + g;
            const uint2 vbh = *(const uint2*)&Bs[buf][0][n * SA + 2 * tg];
            const uint2 vbl = *(const uint2*)&Bs[buf][1][n * SA + 2 * tg];
            #pragma unroll
            for (int mt = 0; mt < 2; mt++) {
                mma_bf16(acc[mt][nt], fah[mt], vbh.x, vbh.y);   // hi*hi
                mma_bf16(acc[mt][nt], fah[mt], vbl.x, vbl.y);   // hi*lo
                mma_bf16(acc[mt][nt], fal[mt], vbh.x, vbh.y);   // lo*hi
            }
        }

        if (has_next) {
            const int nb = buf ^ 1;
            store_smem(nb);
            __syncthreads();
            buf = nb;
        }
    }

    // epilogue
    #pragma unroll
    for (int mt = 0; mt < 2; mt++) {
        const int r0 = bm + m0 + mt * 16 + g;
        #pragma unroll
        for (int nt = 0; nt < 4; nt++) {
            const int cc = bn + n0 + nt * 8 + tg * 2;
            float v0 = acc[mt][nt][0], v1 = acc[mt][nt][1];
            float v2 = acc[mt][nt][2], v3 = acc[mt][nt][3];
            if (ACT == 1) { v0 = phi_f(v0); v1 = phi_f(v1); v2 = phi_f(v2); v3 = phi_f(v3); }
            *(float2*)(C + (size_t)r0 * ND + cc)       = make_float2(v0, v1);
            *(float2*)(C + (size_t)(r0 + 8) * ND + cc) = make_float2(v2, v3);
        }
    }
}

// ---------------------------------------------------------------------------
// Kv / K1 split-K partials (fp32 FFMA; tiny vs the GEMMs).
// ---------------------------------------------------------------------------
__global__ void __launch_bounds__(256)
kv_partial_k()
{
    const int chunk = blockIdx.x;
    const int h = blockIdx.y;
    const int b = blockIdx.z;
    const int tid = threadIdx.x;

    __shared__ float Ks[32][64];
    __shared__ float Vs[32][64];

    const size_t base = (size_t)b * L_ * D_ + (size_t)h * DH;
    const int l0 = chunk * CHL;

    const int mt = (tid >> 4) * 4;
    const int nt = (tid & 15) * 4;

    float acc[4][4];
    #pragma unroll
    for (int i = 0; i < 4; i++)
        #pragma unroll
        for (int j = 0; j < 4; j++) acc[i][j] = 0.f;
    float k1 = 0.f;

    for (int sub = 0; sub < CHL / 32; sub++) {
        const int lbase = l0 + sub * 32;
        __syncthreads();
        #pragma unroll
        for (int i = 0; i < 2; i++) {
            const int f = tid + i * 256;
            const int r = f >> 4;
            const int c = (f & 15) * 4;
            const size_t off = base + (size_t)(lbase + r) * D_ + c;
            *(float4*)&Ks[r][c] = *(const float4*)(g_Kf + off);
            *(float4*)&Vs[r][c] = *(const float4*)(g_V + off);
        }
        __syncthreads();

        #pragma unroll 8
        for (int l = 0; l < 32; l++) {
            float a[4], v[4];
            *(float4*)a = *(const float4*)&Ks[l][mt];
            *(float4*)v = *(const float4*)&Vs[l][nt];
            #pragma unroll
            for (int i = 0; i < 4; i++)
                #pragma unroll
                for (int j = 0; j < 4; j++) acc[i][j] += a[i] * v[j];
        }
        if (tid < DH) {
            #pragma unroll 8
            for (int l = 0; l < 32; l++) k1 += Ks[l][tid];
        }
    }

    const int bh = b * H_ + h;
    float* outp = g_KvPart + (size_t)(bh * LCH + chunk) * (DH * DH);
    #pragma unroll
    for (int i = 0; i < 4; i++)
        #pragma unroll
        for (int j = 0; j < 4; j++)
            outp[(mt + i) * DH + (nt + j)] = acc[i][j];
    if (tid < DH)
        g_K1Part[(size_t)(bh * LCH + chunk) * DH + tid] = k1;
}

__global__ void __launch_bounds__(256)
kv_reduce_k()
{
    const int bh = blockIdx.x;
    const int tid = threadIdx.x;
    for (int e = tid; e < DH * DH; e += 256) {
        float s = 0.f;
        #pragma unroll
        for (int c = 0; c < LCH; c++)
            s += g_KvPart[(size_t)(bh * LCH + c) * (DH * DH) + e];
        g_Kv[(size_t)bh * DH * DH + e] = s;
    }
    if (tid < DH) {
        float s = 0.f;
        #pragma unroll
        for (int c = 0; c < LCH; c++)
            s += g_K1Part[(size_t)(bh * LCH + c) * DH + tid];
        g_K1[(size_t)bh * DH + tid] = s;
    }
}

// ---------------------------------------------------------------------------
// num/den apply; emits attention output directly as (bf16 hi, bf16 lo).
// ---------------------------------------------------------------------------
__global__ void __launch_bounds__(128)
attn_apply_k()
{
    const int lt = blockIdx.x;
    const int h = blockIdx.y;
    const int b = blockIdx.z;
    const int tid = threadIdx.x;
    const int bh = b * H_ + h;

    __shared__ float Kvs[DH][DH];
    __shared__ float K1s[DH];

    #pragma unroll
    for (int i = 0; i < 8; i++) {
        const int f = tid + i * 128;
        ((float4*)Kvs)[f] = ((const float4*)(g_Kv + (size_t)bh * DH * DH))[f];
    }
    if (tid < 16)
        ((float4*)K1s)[tid] = ((const float4*)(g_K1 + (size_t)bh * DH))[tid];
    __syncthreads();

    const int l = lt * 128 + tid;
    const float* qrow = g_Qf + ((size_t)b * L_ + l) * D_ + (size_t)h * DH;

    float q[64];
    #pragma unroll
    for (int i = 0; i < 16; i++) {
        float4 v = *(const float4*)(qrow + i * 4);
        q[i * 4 + 0] = v.x; q[i * 4 + 1] = v.y;
        q[i * 4 + 2] = v.z; q[i * 4 + 3] = v.w;
    }

    float den = 1e-6f;
    #pragma unroll
    for (int m = 0; m < 64; m++) den += q[m] * K1s[m];
    const float invden = 1.0f / den;

    const size_t obase = ((size_t)b * L_ + l) * D_ + (size_t)h * DH;
    for (int n0 = 0; n0 < 64; n0 += 8) {
        float acc[8];
        #pragma unroll
        for (int j = 0; j < 8; j++) acc[j] = 0.f;
        #pragma unroll
        for (int m = 0; m < 64; m++) {
            const float qm = q[m];
            #pragma unroll
            for (int j = 0; j < 8; j++) acc[j] += qm * Kvs[m][n0 + j];
        }
        #pragma unroll
        for (int j = 0; j < 8; j++) {
            const float v = acc[j] * invden;
            const __nv_bfloat16 hh = __float2bfloat16(v);
            g_ah[obase + n0 + j] = hh;
            g_al[obase + n0 + j] = __float2bfloat16(v - __bfloat162float(hh));
        }
    }
}

// ---------------------------------------------------------------------------
// Launch sequence.
// ---------------------------------------------------------------------------
extern "C" void kernel_launch(void* const* d_in, const int* in_sizes, int n_in,
                              void* d_out, int out_size)
{
    const float* x  = (const float*)d_in[0];
    const float* Wq = (const float*)d_in[1];
    const float* Wk = (const float*)d_in[2];
    const float* Wv = (const float*)d_in[3];
    const float* Wo = (const float*)d_in[4];
    float* out = (float*)d_out;

    // hi/lo bf16 splits
    convert_k<0><<<(M_ * D_ / 4 + 255) / 256, 256>>>(x,  M_ * D_ / 4);
    convert_k<1><<<(D_ * D_ / 4 + 255) / 256, 256>>>(Wq, D_ * D_ / 4);
    convert_k<2><<<(D_ * D_ / 4 + 255) / 256, 256>>>(Wk, D_ * D_ / 4);
    convert_k<3><<<(D_ * D_ / 4 + 255) / 256, 256>>>(Wv, D_ * D_ / 4);
    convert_k<4><<<(D_ * D_ / 4 + 255) / 256, 256>>>(Wo, D_ * D_ / 4);

    dim3 gg(ND / 128, M_ / 128);   // (8, 256)

    // Projections (phi fused into Q/K epilogues)
    bgemm_k<1, 0, 0, 0><<<gg, 512>>>(nullptr);   // Qf = phi(x@Wq)
    bgemm_k<1, 0, 1, 1><<<gg, 512>>>(nullptr);   // Kf = phi(x@Wk)
    bgemm_k<0, 0, 2, 2><<<gg, 512>>>(nullptr);   // V  = x@Wv

    // Kv = Kf^T @ V, K1 = sum_l Kf (split-K + deterministic reduce)
    kv_partial_k<<<dim3(LCH, H_, B_), 256>>>();
    kv_reduce_k<<<B_ * H_, 256>>>();

    // num/den + head re-interleave; writes bf16 hi/lo attention output
    attn_apply_k<<<dim3(L_ / 128, H_, B_), 128>>>();

    // Output projection: attn @ Wo -> d_out
    bgemm_k<0, 1, 3, 3><<<gg, 512>>>(out);
}

// round 17
// speedup vs baseline: 1.2570x; 1.2570x over previous
#include <cuda_runtime.h>
#include <cuda_bf16.h>
#include <cstdint>
#include <math.h>

// Problem constants (fixed by the reference: B=4, L=8192, D=1024, H=16)
#define B_   4
#define L_   8192
#define D_   1024
#define H_   16
#define DH   64
#define M_   (B_*L_)          // 32768 rows
#define KD   1024             // GEMM K dim
#define ND   1024             // GEMM N dim
#define LCH  16               // split-K chunks over L for the Kv reduction
#define CHL  (L_/LCH)         // 512 rows per chunk

// ---------------------------------------------------------------------------
// Scratch: __device__ globals (allocation-free per harness rules)
// ---------------------------------------------------------------------------
__device__ float g_Qf[(size_t)M_*D_];     // phi(Q) fp32
__device__ float g_Kf[(size_t)M_*D_];     // phi(K) fp32
__device__ float g_V [(size_t)M_*D_];     // V fp32
__device__ float g_KvPart[(size_t)B_*H_*LCH*DH*DH];
__device__ float g_K1Part[(size_t)B_*H_*LCH*DH];
__device__ float g_Kv[(size_t)B_*H_*DH*DH];
__device__ float g_K1[(size_t)B_*H_*DH];

// bf16 hi/lo split operands for tensor-core GEMMs
__device__ __nv_bfloat16 g_xh[(size_t)M_*D_], g_xl[(size_t)M_*D_];   // x
__device__ __nv_bfloat16 g_ah[(size_t)M_*D_], g_al[(size_t)M_*D_];   // attn out
__device__ __nv_bfloat16 g_Wh[4][(size_t)D_*D_], g_Wl[4][(size_t)D_*D_];

__device__ __forceinline__ float phi_f(float x) {
    return (x > 0.f) ? (x + 1.f) : expf(x);   // elu(x)+1
}

// ---------------------------------------------------------------------------
// fp32 -> (bf16 hi, bf16 lo) split conversion.  DST: 0=x, 1..4=W[DST-1]
// ---------------------------------------------------------------------------
template<int DST>
__global__ void __launch_bounds__(256)
convert_k(const float* __restrict__ src, int n4)
{
    __nv_bfloat16* hi = (DST == 0) ? g_xh
                      : (DST == 1) ? g_Wh[0]
                      : (DST == 2) ? g_Wh[1]
                      : (DST == 3) ? g_Wh[2] : g_Wh[3];
    __nv_bfloat16* lo = (DST == 0) ? g_xl
                      : (DST == 1) ? g_Wl[0]
                      : (DST == 2) ? g_Wl[1]
                      : (DST == 3) ? g_Wl[2] : g_Wl[3];

    int i = blockIdx.x * 256 + threadIdx.x;
    if (i >= n4) return;
    float4 v = ((const float4*)src)[i];

    __nv_bfloat16 h0 = __float2bfloat16(v.x);
    __nv_bfloat16 h1 = __float2bfloat16(v.y);
    __nv_bfloat16 h2 = __float2bfloat16(v.z);
    __nv_bfloat16 h3 = __float2bfloat16(v.w);
    __nv_bfloat16 l0 = __float2bfloat16(v.x - __bfloat162float(h0));
    __nv_bfloat16 l1 = __float2bfloat16(v.y - __bfloat162float(h1));
    __nv_bfloat16 l2 = __float2bfloat16(v.z - __bfloat162float(h2));
    __nv_bfloat16 l3 = __float2bfloat16(v.w - __bfloat162float(h3));

    __nv_bfloat162 hp0(h0, h1), hp1(h2, h3), lp0(l0, l1), lp1(l2, l3);
    uint2 hu, lu;
    hu.x = *reinterpret_cast<uint32_t*>(&hp0);
    hu.y = *reinterpret_cast<uint32_t*>(&hp1);
    lu.x = *reinterpret_cast<uint32_t*>(&lp0);
    lu.y = *reinterpret_cast<uint32_t*>(&lp1);
    ((uint2*)hi)[i] = hu;
    ((uint2*)lo)[i] = lu;
}

// ---------------------------------------------------------------------------
// bf16-split tensor-core GEMM: C[M,N] = A@B with A=(Ah+Al), B=(Bh+Bl),
// C = Ah*Bh + Ah*Bl + Al*Bh, fp32 accum via mma.sync.m16n8k16.
// CTA: 256 thr, tile 128x128, kstep=16, double-buffered smem.
// Warp tile 32(m) x 64(n): warps laid out 4(m) x 2(n).
// __launch_bounds__(256,2): cap regs at 128 so 2 CTAs co-reside per SM
// (16 warps/SM as two independent barrier domains) to hide LDS->HMMA latency.
// ---------------------------------------------------------------------------
__device__ __forceinline__ void mma_bf16(float* acc, const uint32_t* a,
                                         uint32_t b0, uint32_t b1)
{
    asm volatile(
        "mma.sync.aligned.m16n8k16.row.col.f32.bf16.bf16.f32 "
        "{%0,%1,%2,%3}, {%4,%5,%6,%7}, {%8,%9}, {%0,%1,%2,%3};\n"
        : "+f"(acc[0]), "+f"(acc[1]), "+f"(acc[2]), "+f"(acc[3])
        : "r"(a[0]), "r"(a[1]), "r"(a[2]), "r"(a[3]), "r"(b0), "r"(b1));
}

#define SA 9   // padded u32 row stride in smem (8 k-pairs + 1 pad)

template<int ACT, int ASRC, int WIDX, int DST>
__global__ void __launch_bounds__(256, 2)
bgemm_k(float* __restrict__ C_ext)
{
    const uint32_t* Ah32 = (const uint32_t*)((ASRC == 0) ? g_xh : g_ah);
    const uint32_t* Al32 = (const uint32_t*)((ASRC == 0) ? g_xl : g_al);
    const __nv_bfloat16* Wh = g_Wh[WIDX];
    const __nv_bfloat16* Wl = g_Wl[WIDX];
    float* C = (DST == 0) ? (float*)g_Qf
             : (DST == 1) ? (float*)g_Kf
             : (DST == 2) ? (float*)g_V
             : C_ext;

    // smem: [stage][hi/lo][128 * SA]  (A m-major, B n-major; k-pairs packed u32)
    __shared__ uint32_t As[2][2][128 * SA];
    __shared__ uint32_t Bs[2][2][128 * SA];

    const int tid = threadIdx.x;
    const int bn = blockIdx.x * 128;
    const int bm = blockIdx.y * 128;

    const int warp = tid >> 5;
    const int lane = tid & 31;
    const int m0 = (warp & 3) * 32;    // warp m offset
    const int n0 = (warp >> 2) * 64;   // warp n offset
    const int g  = lane >> 2;          // group id (0..7)
    const int tg = lane & 3;           // thread-in-group

    // A load mapping: u32 idx i = tid + 256j -> row=(tid>>3)+32j, kp=tid&7
    const int ar = tid >> 3;
    const int akp = tid & 7;
    // B load mapping: u32 idx i = tid + 256j -> k=(tid>>6)+4j, n-pair=(tid&63)
    const int bk = tid >> 6;
    const int bn2 = (tid & 63) * 2;

    float acc[2][8][4];
    #pragma unroll
    for (int mt = 0; mt < 2; mt++)
        #pragma unroll
        for (int nt = 0; nt < 8; nt++)
            #pragma unroll
            for (int e = 0; e < 4; e++) acc[mt][nt][e] = 0.f;

    uint32_t pah[4], pal[4], pbh[4], pbl[4];

    // ---- load one k-slab (kk) into regs ----
    auto load_regs = [&](int kk) {
        #pragma unroll
        for (int j = 0; j < 4; j++) {
            const int row = ar + 32 * j;
            const size_t gi = (size_t)(bm + row) * (KD / 2) + (kk >> 1) + akp;
            pah[j] = Ah32[gi];
            pal[j] = Al32[gi];
        }
        #pragma unroll
        for (int j = 0; j < 4; j++) {
            const int kkk = bk + 4 * j;
            const size_t gi = (size_t)(kk + kkk) * ND + bn + bn2;
            pbh[j] = *(const uint32_t*)(Wh + gi);
            pbl[j] = *(const uint32_t*)(Wl + gi);
        }
    };

    // ---- commit regs to smem stage s ----
    auto store_smem = [&](int s) {
        #pragma unroll
        for (int j = 0; j < 4; j++) {
            const int row = ar + 32 * j;
            As[s][0][row * SA + akp] = pah[j];
            As[s][1][row * SA + akp] = pal[j];
        }
        uint16_t* B0 = (uint16_t*)&Bs[s][0][0];
        uint16_t* B1 = (uint16_t*)&Bs[s][1][0];
        #pragma unroll
        for (int j = 0; j < 4; j++) {
            const int kkk = bk + 4 * j;
            B0[(bn2)     * (2 * SA) + kkk] = (uint16_t)(pbh[j] & 0xFFFF);
            B0[(bn2 + 1) * (2 * SA) + kkk] = (uint16_t)(pbh[j] >> 16);
            B1[(bn2)     * (2 * SA) + kkk] = (uint16_t)(pbl[j] & 0xFFFF);
            B1[(bn2 + 1) * (2 * SA) + kkk] = (uint16_t)(pbl[j] >> 16);
        }
    };

    // prologue
    load_regs(0);
    store_smem(0);
    __syncthreads();

    int buf = 0;
    for (int k0 = 0; k0 < KD; k0 += 16) {
        const bool has_next = (k0 + 16) < KD;
        if (has_next) load_regs(k0 + 16);

        // A fragments (hi & lo) for both m-tiles
        uint32_t fah[2][4], fal[2][4];
        #pragma unroll
        for (int mt = 0; mt < 2; mt++) {
            const int r = m0 + mt * 16 + g;
            fah[mt][0] = As[buf][0][r * SA + tg];
            fah[mt][1] = As[buf][0][(r + 8) * SA + tg];
            fah[mt][2] = As[buf][0][r * SA + tg + 4];
            fah[mt][3] = As[buf][0][(r + 8) * SA + tg + 4];
            fal[mt][0] = As[buf][1][r * SA + tg];
            fal[mt][1] = As[buf][1][(r + 8) * SA + tg];
            fal[mt][2] = As[buf][1][r * SA + tg + 4];
            fal[mt][3] = As[buf][1][(r + 8) * SA + tg + 4];
        }

        #pragma unroll
        for (int nt = 0; nt < 8; nt++) {
            const int n = n0 + nt * 8 + g;
            const uint32_t bh0 = Bs[buf][0][n * SA + tg];
            const uint32_t bh1 = Bs[buf][0][n * SA + tg + 4];
            const uint32_t bl0 = Bs[buf][1][n * SA + tg];
            const uint32_t bl1 = Bs[buf][1][n * SA + tg + 4];
            #pragma unroll
            for (int mt = 0; mt < 2; mt++) {
                mma_bf16(acc[mt][nt], fah[mt], bh0, bh1);   // hi*hi
                mma_bf16(acc[mt][nt], fah[mt], bl0, bl1);   // hi*lo
                mma_bf16(acc[mt][nt], fal[mt], bh0, bh1);   // lo*hi
            }
        }

        if (has_next) {
            const int nb = buf ^ 1;
            store_smem(nb);
            __syncthreads();
            buf = nb;
        }
    }

    // epilogue
    #pragma unroll
    for (int mt = 0; mt < 2; mt++) {
        const int r0 = bm + m0 + mt * 16 + g;
        #pragma unroll
        for (int nt = 0; nt < 8; nt++) {
            const int cc = bn + n0 + nt * 8 + tg * 2;
            float v0 = acc[mt][nt][0], v1 = acc[mt][nt][1];
            float v2 = acc[mt][nt][2], v3 = acc[mt][nt][3];
            if (ACT == 1) { v0 = phi_f(v0); v1 = phi_f(v1); v2 = phi_f(v2); v3 = phi_f(v3); }
            *(float2*)(C + (size_t)r0 * ND + cc)       = make_float2(v0, v1);
            *(float2*)(C + (size_t)(r0 + 8) * ND + cc) = make_float2(v2, v3);
        }
    }
}

// ---------------------------------------------------------------------------
// Kv / K1 split-K partials (fp32 FFMA; tiny vs the GEMMs).
// ---------------------------------------------------------------------------
__global__ void __launch_bounds__(256)
kv_partial_k()
{
    const int chunk = blockIdx.x;
    const int h = blockIdx.y;
    const int b = blockIdx.z;
    const int tid = threadIdx.x;

    __shared__ float Ks[32][64];
    __shared__ float Vs[32][64];

    const size_t base = (size_t)b * L_ * D_ + (size_t)h * DH;
    const int l0 = chunk * CHL;

    const int mt = (tid >> 4) * 4;
    const int nt = (tid & 15) * 4;

    float acc[4][4];
    #pragma unroll
    for (int i = 0; i < 4; i++)
        #pragma unroll
        for (int j = 0; j < 4; j++) acc[i][j] = 0.f;
    float k1 = 0.f;

    for (int sub = 0; sub < CHL / 32; sub++) {
        const int lbase = l0 + sub * 32;
        __syncthreads();
        #pragma unroll
        for (int i = 0; i < 2; i++) {
            const int f = tid + i * 256;
            const int r = f >> 4;
            const int c = (f & 15) * 4;
            const size_t off = base + (size_t)(lbase + r) * D_ + c;
            *(float4*)&Ks[r][c] = *(const float4*)(g_Kf + off);
            *(float4*)&Vs[r][c] = *(const float4*)(g_V + off);
        }
        __syncthreads();

        #pragma unroll 8
        for (int l = 0; l < 32; l++) {
            float a[4], v[4];
            *(float4*)a = *(const float4*)&Ks[l][mt];
            *(float4*)v = *(const float4*)&Vs[l][nt];
            #pragma unroll
            for (int i = 0; i < 4; i++)
                #pragma unroll
                for (int j = 0; j < 4; j++) acc[i][j] += a[i] * v[j];
        }
        if (tid < DH) {
            #pragma unroll 8
            for (int l = 0; l < 32; l++) k1 += Ks[l][tid];
        }
    }

    const int bh = b * H_ + h;
    float* outp = g_KvPart + (size_t)(bh * LCH + chunk) * (DH * DH);
    #pragma unroll
    for (int i = 0; i < 4; i++)
        #pragma unroll
        for (int j = 0; j < 4; j++)
            outp[(mt + i) * DH + (nt + j)] = acc[i][j];
    if (tid < DH)
        g_K1Part[(size_t)(bh * LCH + chunk) * DH + tid] = k1;
}

__global__ void __launch_bounds__(256)
kv_reduce_k()
{
    const int bh = blockIdx.x;
    const int tid = threadIdx.x;
    for (int e = tid; e < DH * DH; e += 256) {
        float s = 0.f;
        #pragma unroll
        for (int c = 0; c < LCH; c++)
            s += g_KvPart[(size_t)(bh * LCH + c) * (DH * DH) + e];
        g_Kv[(size_t)bh * DH * DH + e] = s;
    }
    if (tid < DH) {
        float s = 0.f;
        #pragma unroll
        for (int c = 0; c < LCH; c++)
            s += g_K1Part[(size_t)(bh * LCH + c) * DH + tid];
        g_K1[(size_t)bh * DH + tid] = s;
    }
}

// ---------------------------------------------------------------------------
// num/den apply; emits attention output directly as (bf16 hi, bf16 lo).
// ---------------------------------------------------------------------------
__global__ void __launch_bounds__(128)
attn_apply_k()
{
    const int lt = blockIdx.x;
    const int h = blockIdx.y;
    const int b = blockIdx.z;
    const int tid = threadIdx.x;
    const int bh = b * H_ + h;

    __shared__ float Kvs[DH][DH];
    __shared__ float K1s[DH];

    #pragma unroll
    for (int i = 0; i < 8; i++) {
        const int f = tid + i * 128;
        ((float4*)Kvs)[f] = ((const float4*)(g_Kv + (size_t)bh * DH * DH))[f];
    }
    if (tid < 16)
        ((float4*)K1s)[tid] = ((const float4*)(g_K1 + (size_t)bh * DH))[tid];
    __syncthreads();

    const int l = lt * 128 + tid;
    const float* qrow = g_Qf + ((size_t)b * L_ + l) * D_ + (size_t)h * DH;

    float q[64];
    #pragma unroll
    for (int i = 0; i < 16; i++) {
        float4 v = *(const float4*)(qrow + i * 4);
        q[i * 4 + 0] = v.x; q[i * 4 + 1] = v.y;
        q[i * 4 + 2] = v.z; q[i * 4 + 3] = v.w;
    }

    float den = 1e-6f;
    #pragma unroll
    for (int m = 0; m < 64; m++) den += q[m] * K1s[m];
    const float invden = 1.0f / den;

    const size_t obase = ((size_t)b * L_ + l) * D_ + (size_t)h * DH;
    for (int n0 = 0; n0 < 64; n0 += 8) {
        float acc[8];
        #pragma unroll
        for (int j = 0; j < 8; j++) acc[j] = 0.f;
        #pragma unroll
        for (int m = 0; m < 64; m++) {
            const float qm = q[m];
            #pragma unroll
            for (int j = 0; j < 8; j++) acc[j] += qm * Kvs[m][n0 + j];
        }
        #pragma unroll
        for (int j = 0; j < 8; j++) {
            const float v = acc[j] * invden;
            const __nv_bfloat16 hh = __float2bfloat16(v);
            g_ah[obase + n0 + j] = hh;
            g_al[obase + n0 + j] = __float2bfloat16(v - __bfloat162float(hh));
        }
    }
}

// ---------------------------------------------------------------------------
// Launch sequence.
// ---------------------------------------------------------------------------
extern "C" void kernel_launch(void* const* d_in, const int* in_sizes, int n_in,
                              void* d_out, int out_size)
{
    const float* x  = (const float*)d_in[0];
    const float* Wq = (const float*)d_in[1];
    const float* Wk = (const float*)d_in[2];
    const float* Wv = (const float*)d_in[3];
    const float* Wo = (const float*)d_in[4];
    float* out = (float*)d_out;

    // hi/lo bf16 splits
    convert_k<0><<<(M_ * D_ / 4 + 255) / 256, 256>>>(x,  M_ * D_ / 4);
    convert_k<1><<<(D_ * D_ / 4 + 255) / 256, 256>>>(Wq, D_ * D_ / 4);
    convert_k<2><<<(D_ * D_ / 4 + 255) / 256, 256>>>(Wk, D_ * D_ / 4);
    convert_k<3><<<(D_ * D_ / 4 + 255) / 256, 256>>>(Wv, D_ * D_ / 4);
    convert_k<4><<<(D_ * D_ / 4 + 255) / 256, 256>>>(Wo, D_ * D_ / 4);

    dim3 gg(ND / 128, M_ / 128);   // (8, 256)

    // Projections (phi fused into Q/K epilogues)
    bgemm_k<1, 0, 0, 0><<<gg, 256>>>(nullptr);   // Qf = phi(x@Wq)
    bgemm_k<1, 0, 1, 1><<<gg, 256>>>(nullptr);   // Kf = phi(x@Wk)
    bgemm_k<0, 0, 2, 2><<<gg, 256>>>(nullptr);   // V  = x@Wv

    // Kv = Kf^T @ V, K1 = sum_l Kf (split-K + deterministic reduce)
    kv_partial_k<<<dim3(LCH, H_, B_), 256>>>();
    kv_reduce_k<<<B_ * H_, 256>>>();

    // num/den + head re-interleave; writes bf16 hi/lo attention output
    attn_apply_k<<<dim3(L_ / 128, H_, B_), 128>>>();

    // Output projection: attn @ Wo -> d_out
    bgemm_k<0, 1, 3, 3><<<gg, 256>>>(out);
}